// round 4
// baseline (speedup 1.0000x reference)
#include <cuda_runtime.h>

#define BB 16      // batches
#define NP 2048    // points per batch
#define NC 64      // feature channels
#define NS 512     // fps samples
#define NK 24      // knn k

// scratch (no allocation allowed)
__device__ int    g_fidx[BB * NS];
__device__ int    g_gidx[BB * NS * NK];
__device__ double g_sum[BB];
__device__ double g_sq[BB];

// ---------------------------------------------------------------------------
// Furthest point sampling: one block per batch, 1024 threads, 2 points/thread.
// Bit-exact vs reference (verified R1: outputs 0/1 matched exactly).
// ---------------------------------------------------------------------------
__global__ __launch_bounds__(1024, 1)
void fps_kernel(const float* __restrict__ pts,
                float* __restrict__ out_idx,   // may be null
                float* __restrict__ out_sp) {  // may be null
    const int b = blockIdx.x;
    const float* P = pts + b * NP * 3;

    __shared__ float sp[NP * 3];   // 24 KB
    __shared__ float swv[32];
    __shared__ int   swi[32];
    __shared__ int   s_cur;

    const int t = threadIdx.x;
    for (int i = t; i < NP * 3; i += 1024) sp[i] = P[i];
    __syncthreads();

    const int t1 = t + 1024;
    const float px0 = sp[3*t],  py0 = sp[3*t+1],  pz0 = sp[3*t+2];
    const float px1 = sp[3*t1], py1 = sp[3*t1+1], pz1 = sp[3*t1+2];
    float m0 = 1e10f, m1 = 1e10f;
    int cur = 0;
    const int lane = t & 31, wid = t >> 5;

    for (int it = 0; it < NS; ++it) {
        const float cx = sp[3*cur], cy = sp[3*cur+1], cz = sp[3*cur+2];
        if (t == 0) {
            g_fidx[b * NS + it] = cur;
            if (out_idx) out_idx[b * NS + it] = (float)cur;
            if (out_sp) {
                float* o = out_sp + (b * NS + it) * 3;
                o[0] = cx; o[1] = cy; o[2] = cz;
            }
        }
        // distances, exact reference association: ((dx*dx + dy*dy) + dz*dz)
        {
            float dx = px0 - cx, dy = py0 - cy, dz = pz0 - cz;
            float d = __fadd_rn(__fadd_rn(__fmul_rn(dx,dx), __fmul_rn(dy,dy)), __fmul_rn(dz,dz));
            m0 = fminf(m0, d);
        }
        {
            float dx = px1 - cx, dy = py1 - cy, dz = pz1 - cz;
            float d = __fadd_rn(__fadd_rn(__fmul_rn(dx,dx), __fmul_rn(dy,dy)), __fmul_rn(dz,dz));
            m1 = fminf(m1, d);
        }
        // local argmax: tie -> lower index (t < t1)
        float bv; int bi;
        if (m0 >= m1) { bv = m0; bi = t; } else { bv = m1; bi = t1; }
        #pragma unroll
        for (int off = 16; off > 0; off >>= 1) {
            float ov = __shfl_down_sync(0xffffffffu, bv, off);
            int   oi = __shfl_down_sync(0xffffffffu, bi, off);
            if (ov > bv || (ov == bv && oi < bi)) { bv = ov; bi = oi; }
        }
        if (lane == 0) { swv[wid] = bv; swi[wid] = bi; }
        __syncthreads();
        if (wid == 0) {
            bv = swv[lane]; bi = swi[lane];
            #pragma unroll
            for (int off = 16; off > 0; off >>= 1) {
                float ov = __shfl_down_sync(0xffffffffu, bv, off);
                int   oi = __shfl_down_sync(0xffffffffu, bi, off);
                if (ov > bv || (ov == bv && oi < bi)) { bv = ov; bi = oi; }
            }
            if (lane == 0) s_cur = bi;
        }
        __syncthreads();
        cur = s_cur;
    }
}

// ---------------------------------------------------------------------------
// kNN: one block per (batch, sample). Distances cached in regs, 24 rounds of
// stable argmin (tie -> lower index) to match XLA top_k(-dist).
// d1/d2 = mul/add sum-of-squares (XLA reduce, no contraction — verified by FPS);
// d3 = FMA chain (cublas K-loop: acc = fma(sk, pk, acc), k ascending).
// dist = (d1 + d2) - 2*d3 (mul by 2 is exact; sub exact op).
// ---------------------------------------------------------------------------
__global__ __launch_bounds__(256)
void knn_kernel(const float* __restrict__ pts) {
    const int b = blockIdx.y;
    const int s = blockIdx.x;
    const int t = threadIdx.x;   // 256
    const float* P = pts + b * NP * 3;

    __shared__ float sv[8];
    __shared__ int   si[8];
    __shared__ int   s_sel;

    const int qi = g_fidx[b * NS + s];
    const float sx = P[3*qi], sy = P[3*qi+1], sz = P[3*qi+2];
    const float d2 = __fadd_rn(__fadd_rn(__fmul_rn(sx,sx), __fmul_rn(sy,sy)), __fmul_rn(sz,sz));

    float d[8];
    #pragma unroll
    for (int i = 0; i < 8; ++i) {
        const int n = t * 8 + i;
        const float px = P[3*n], py = P[3*n+1], pz = P[3*n+2];
        const float d1 = __fadd_rn(__fadd_rn(__fmul_rn(px,px), __fmul_rn(py,py)), __fmul_rn(pz,pz));
        // cublas-style fma chain over k = x, y, z
        const float d3 = __fmaf_rn(sz, pz, __fmaf_rn(sy, py, __fmul_rn(sx, px)));
        d[i] = __fsub_rn(__fadd_rn(d1, d2), __fmul_rn(2.0f, d3));
    }

    const int lane = t & 31, wid = t >> 5;
    int* gout = g_gidx + (b * NS + s) * NK;

    for (int r = 0; r < NK; ++r) {
        float bv = 3.4e38f; int bi = 1 << 30;
        #pragma unroll
        for (int i = 0; i < 8; ++i) {   // ascending index -> stable
            if (d[i] < bv) { bv = d[i]; bi = t * 8 + i; }
        }
        #pragma unroll
        for (int off = 16; off > 0; off >>= 1) {
            float ov = __shfl_down_sync(0xffffffffu, bv, off);
            int   oi = __shfl_down_sync(0xffffffffu, bi, off);
            if (ov < bv || (ov == bv && oi < bi)) { bv = ov; bi = oi; }
        }
        if (lane == 0) { sv[wid] = bv; si[wid] = bi; }
        __syncthreads();
        if (t == 0) {
            bv = sv[0]; bi = si[0];
            #pragma unroll
            for (int w = 1; w < 8; ++w) {
                if (sv[w] < bv || (sv[w] == bv && si[w] < bi)) { bv = sv[w]; bi = si[w]; }
            }
            s_sel = bi;
            gout[r] = bi;
        }
        __syncthreads();
        const int sel = s_sel;
        if ((sel >> 3) == t) d[sel & 7] = 3.4e38f;   // owner removes, private regs
    }
}

// ---------------------------------------------------------------------------
// per-batch sum / sumsq of centered = feat[gidx] - feat[fidx]
// (double accumulation -> std accurate to ~1e-9 rel)
// ---------------------------------------------------------------------------
__global__ void zero_kernel() {
    const int t = threadIdx.x;
    if (t < BB) { g_sum[t] = 0.0; g_sq[t] = 0.0; }
}

__global__ __launch_bounds__(256)
void stats_kernel(const float* __restrict__ feat) {
    const int b = blockIdx.y;
    const float* F = feat + b * NP * NC;
    const int tid = blockIdx.x * 256 + threadIdx.x;   // 64*256 = 16384 threads
    const int STRIDE = 64 * 256;
    const int TOTB = NS * NK * NC;    // 786432

    double s = 0.0, q = 0.0;
    for (int e = tid; e < TOTB; e += STRIDE) {
        const int c  = e & 63;
        const int sj = e >> 6;
        const int j  = sj % NK;
        const int ss = sj / NK;
        const int gi = g_gidx[(b * NS + ss) * NK + j];
        const int fi = g_fidx[b * NS + ss];
        const float v = F[gi * NC + c] - F[fi * NC + c];
        s += (double)v;
        q += (double)v * (double)v;
    }
    const int lane = threadIdx.x & 31, wid = threadIdx.x >> 5;
    #pragma unroll
    for (int off = 16; off > 0; off >>= 1) {
        s += __shfl_down_sync(0xffffffffu, s, off);
        q += __shfl_down_sync(0xffffffffu, q, off);
    }
    __shared__ double ws[8], wq[8];
    if (lane == 0) { ws[wid] = s; wq[wid] = q; }
    __syncthreads();
    if (threadIdx.x == 0) {
        double ts = ws[0], tq = wq[0];
        #pragma unroll
        for (int w = 1; w < 8; ++w) { ts += ws[w]; tq += wq[w]; }
        atomicAdd(&g_sum[b], ts);
        atomicAdd(&g_sq[b], tq);
    }
}

// ---------------------------------------------------------------------------
// finalize (float4 vectorized): 4 channels per thread
//   out[b,s,j, 0:64]   = alpha*(centered/(std+eps)) + beta
//   out[b,s,j, 64:128] = mean (= feat[fidx])
// ---------------------------------------------------------------------------
__global__ __launch_bounds__(256)
void finalize_kernel(const float* __restrict__ feat,
                     const float* __restrict__ alpha,
                     const float* __restrict__ beta,
                     float* __restrict__ out) {
    const int TOT4 = BB * NS * NK * (NC / 4);   // 3,145,728
    const int gid = blockIdx.x * 256 + threadIdx.x;
    if (gid >= TOT4) return;
    const int c4  = gid & 15;               // which float4 of the 64 channels
    const int sj  = gid >> 4;               // b*NS*NK + s*NK + j
    const int b   = sj / (NS * NK);
    const int rem = sj % (NS * NK);
    const int s   = rem / NK;

    const float* F = feat + b * NP * NC;
    const int gi = g_gidx[sj];              // sj == (b*NS+s)*NK + j
    const int fi = g_fidx[b * NS + s];

    const float4 mean = *(const float4*)(F + fi * NC + c4 * 4);
    const float4 gv   = *(const float4*)(F + gi * NC + c4 * 4);
    const float4 al   = *(const float4*)(alpha + c4 * 4);
    const float4 be   = *(const float4*)(beta  + c4 * 4);

    const double Nf  = (double)(NS * NK * NC);
    const double sum = g_sum[b], sq = g_sq[b];
    double var = (sq - sum * sum / Nf) / (Nf - 1.0);
    if (var < 0.0) var = 0.0;
    const float stdv = (float)sqrt(var);
    const float inv = 1.0f / (stdv + 1e-5f);

    float4 gf;
    gf.x = al.x * ((gv.x - mean.x) * inv) + be.x;
    gf.y = al.y * ((gv.y - mean.y) * inv) + be.y;
    gf.z = al.z * ((gv.z - mean.z) * inv) + be.z;
    gf.w = al.w * ((gv.w - mean.w) * inv) + be.w;

    float* o = out + sj * 128;
    *(float4*)(o + c4 * 4)      = gf;
    *(float4*)(o + 64 + c4 * 4) = mean;
}

// ---------------------------------------------------------------------------
extern "C" void kernel_launch(void* const* d_in, const int* in_sizes, int n_in,
                              void* d_out, int out_size) {
    const float* pts   = (const float*)d_in[0];   // 16x2048x3
    const float* feat  = (const float*)d_in[1];   // 16x2048x64
    const float* alpha = (const float*)d_in[2];   // 64
    const float* beta  = (const float*)d_in[3];   // 64
    float* out = (float*)d_out;

    const int SZ_IDX = BB * NS;                   // 8192
    const int SZ_SP  = BB * NS * 3;               // 24576
    const int SZ_OF  = BB * NS * NK * 2 * NC;     // 25165824... (16*512*24*128)

    float* out_idx = nullptr;
    float* out_sp  = nullptr;
    float* out_f   = out;
    if (out_size >= SZ_IDX + SZ_SP + SZ_OF) {
        out_idx = out;
        out_sp  = out + SZ_IDX;
        out_f   = out + SZ_IDX + SZ_SP;
    }

    zero_kernel<<<1, 32>>>();     // independent; hides under fps on the stream

    fps_kernel<<<BB, 1024>>>(pts, out_idx, out_sp);

    dim3 kg(NS, BB);
    knn_kernel<<<kg, 256>>>(pts);

    dim3 sg(64, BB);
    stats_kernel<<<sg, 256>>>(feat);

    const int TOT4 = BB * NS * NK * (NC / 4);
    finalize_kernel<<<(TOT4 + 255) / 256, 256>>>(feat, alpha, beta, out_f);
}

// round 5
// speedup vs baseline: 1.8700x; 1.8700x over previous
#include <cuda_runtime.h>

#define BB 16      // batches
#define NP 2048    // points per batch
#define NC 64      // feature channels
#define NS 512     // fps samples
#define NK 24      // knn k

// scratch (no allocation allowed)
__device__ int    g_fidx[BB * NS];
__device__ int    g_gidx[BB * NS * NK];
__device__ double g_sum[BB];
__device__ double g_sq[BB];

__device__ __forceinline__ unsigned redux_max_u32(unsigned v) {
    unsigned r;
    asm volatile("redux.sync.max.u32 %0, %1, 0xffffffff;" : "=r"(r) : "r"(v));
    return r;
}
__device__ __forceinline__ unsigned redux_min_u32(unsigned v) {
    unsigned r;
    asm volatile("redux.sync.min.u32 %0, %1, 0xffffffff;" : "=r"(r) : "r"(v));
    return r;
}

// ---------------------------------------------------------------------------
// FPS: one block/batch, 512 threads x 4 points. One barrier per iteration:
// warp redux argmax -> lane0 atomicMax into per-iteration slot -> bar -> read.
// Distances & min semantics identical to the verified bit-exact version.
// Key = (min_d_bits << 32) | ~idx : max => max dist, tie => min idx
// (min_d >= 0 always, so float-bit ordering == float ordering).
// ---------------------------------------------------------------------------
__global__ __launch_bounds__(512, 1)
void fps_kernel(const float* __restrict__ pts,
                float* __restrict__ out_idx,   // may be null
                float* __restrict__ out_sp) {  // may be null
    const int b = blockIdx.x;
    __shared__ float sp[NP * 3];                 // 24 KB
    __shared__ unsigned long long slot[NS];      // 4 KB

    const int t = threadIdx.x;
    {
        const float4* src = (const float4*)(pts + b * NP * 3);
        float4* dst = (float4*)sp;
        for (int i = t; i < NP * 3 / 4; i += 512) dst[i] = src[i];
        for (int i = t; i < NS; i += 512) slot[i] = 0ull;
    }
    __syncthreads();

    const int i0 = t, i1 = t + 512, i2 = t + 1024, i3 = t + 1536;
    const float x0 = sp[3*i0], y0 = sp[3*i0+1], z0 = sp[3*i0+2];
    const float x1 = sp[3*i1], y1 = sp[3*i1+1], z1 = sp[3*i1+2];
    const float x2 = sp[3*i2], y2 = sp[3*i2+1], z2 = sp[3*i2+2];
    const float x3 = sp[3*i3], y3 = sp[3*i3+1], z3 = sp[3*i3+2];
    float m0 = 1e10f, m1 = 1e10f, m2 = 1e10f, m3 = 1e10f;
    int cur = 0;

    for (int it = 0; it < NS; ++it) {
        const float cx = sp[3*cur], cy = sp[3*cur+1], cz = sp[3*cur+2];
        if (t == 0) {
            g_fidx[b * NS + it] = cur;
            if (out_idx) out_idx[b * NS + it] = (float)cur;
            if (out_sp) {
                float* o = out_sp + (b * NS + it) * 3;
                o[0] = cx; o[1] = cy; o[2] = cz;
            }
        }
        // exact reference association: ((dx*dx + dy*dy) + dz*dz)
        {
            float dx = x0 - cx, dy = y0 - cy, dz = z0 - cz;
            m0 = fminf(m0, __fadd_rn(__fadd_rn(__fmul_rn(dx,dx), __fmul_rn(dy,dy)), __fmul_rn(dz,dz)));
        }
        {
            float dx = x1 - cx, dy = y1 - cy, dz = z1 - cz;
            m1 = fminf(m1, __fadd_rn(__fadd_rn(__fmul_rn(dx,dx), __fmul_rn(dy,dy)), __fmul_rn(dz,dz)));
        }
        {
            float dx = x2 - cx, dy = y2 - cy, dz = z2 - cz;
            m2 = fminf(m2, __fadd_rn(__fadd_rn(__fmul_rn(dx,dx), __fmul_rn(dy,dy)), __fmul_rn(dz,dz)));
        }
        {
            float dx = x3 - cx, dy = y3 - cy, dz = z3 - cz;
            m3 = fminf(m3, __fadd_rn(__fadd_rn(__fmul_rn(dx,dx), __fmul_rn(dy,dy)), __fmul_rn(dz,dz)));
        }
        const unsigned f0 = __float_as_uint(m0), f1 = __float_as_uint(m1);
        const unsigned f2 = __float_as_uint(m2), f3 = __float_as_uint(m3);
        unsigned lm = max(max(f0, f1), max(f2, f3));
        const unsigned wm = redux_max_u32(lm);
        // candidate index: smallest local index achieving wm (i0<i1<i2<i3)
        unsigned cand = 0xffffffffu;
        if (f3 == wm) cand = (unsigned)i3;
        if (f2 == wm) cand = (unsigned)i2;
        if (f1 == wm) cand = (unsigned)i1;
        if (f0 == wm) cand = (unsigned)i0;
        const unsigned wi = redux_min_u32(cand);
        if ((t & 31) == 0)
            atomicMax(&slot[it], ((unsigned long long)wm << 32) | (unsigned)(~wi));
        __syncthreads();
        cur = (int)(~(unsigned)slot[it]);
    }
}

// ---------------------------------------------------------------------------
// kNN: warp per query, 8 warps/block, no block barriers in the loop.
// Lane l owns candidates n = i*32+l, i=0..63. Keys (monotonic u32 map of the
// float distance) in smem; per-lane group minima (8 groups of 8) + lane best
// cached; each round: 2 redux ops, then only the winning lane rescans 8+8.
// Distance formula identical to the verified kernel:
//   d1,d2 mul/add sum-of-squares; d3 = fma chain; d = (d1+d2) - 2*d3.
// ---------------------------------------------------------------------------
#define KNN_SMEM (NP*3*4 + 8*64*32*4 + 8*8*32*8)   // 24576 + 65536 + 16384 = 106496

__global__ __launch_bounds__(256)
void knn_kernel(const float* __restrict__ pts) {
    extern __shared__ char smem_raw[];
    float* sp = (float*)smem_raw;                                  // 24 KB
    unsigned (*sk)[64][32] = (unsigned (*)[64][32])(smem_raw + NP*3*4);          // 64 KB
    unsigned long long (*sgm)[8][32] =
        (unsigned long long (*)[8][32])(smem_raw + NP*3*4 + 8*64*32*4);          // 16 KB

    const int blk  = blockIdx.x;          // 0..1023
    const int b    = blk >> 6;
    const int sgrp = blk & 63;
    const int t = threadIdx.x, lane = t & 31, w = t >> 5;
    const int s = sgrp * 8 + w;

    {
        const float4* src = (const float4*)(pts + b * NP * 3);
        float4* dst = (float4*)sp;
        for (int i = t; i < NP * 3 / 4; i += 256) dst[i] = src[i];
    }
    __syncthreads();

    const int qi = g_fidx[b * NS + s];
    const float sx = sp[3*qi], sy = sp[3*qi+1], sz = sp[3*qi+2];
    const float d2 = __fadd_rn(__fadd_rn(__fmul_rn(sx,sx), __fmul_rn(sy,sy)), __fmul_rn(sz,sz));

    unsigned long long lb = ~0ull;
    #pragma unroll
    for (int g = 0; g < 8; ++g) {
        unsigned long long gm = ~0ull;
        #pragma unroll
        for (int j = 0; j < 8; ++j) {
            const int i = g * 8 + j;
            const int n = i * 32 + lane;
            const float px = sp[3*n], py = sp[3*n+1], pz = sp[3*n+2];
            const float d1 = __fadd_rn(__fadd_rn(__fmul_rn(px,px), __fmul_rn(py,py)), __fmul_rn(pz,pz));
            const float d3 = __fmaf_rn(sz, pz, __fmaf_rn(sy, py, __fmul_rn(sx, px)));
            const float d  = __fsub_rn(__fadd_rn(d1, d2), __fmul_rn(2.0f, d3));
            const unsigned bits = __float_as_uint(d);
            const unsigned key  = (bits & 0x80000000u) ? ~bits : (bits | 0x80000000u);
            sk[w][i][lane] = key;
            const unsigned long long pk = ((unsigned long long)key << 32) | (unsigned)n;
            gm = min(gm, pk);   // equal key -> lower n wins (low bits)
        }
        sgm[w][g][lane] = gm;
        lb = min(lb, gm);
    }

    int* gout = g_gidx + (b * NS + s) * NK;
    for (int r = 0; r < NK; ++r) {
        const unsigned lbk = (unsigned)(lb >> 32);
        const unsigned wk  = redux_min_u32(lbk);
        const unsigned cand = (lbk == wk) ? (unsigned)lb : 0xffffffffu;  // low = n
        const unsigned wi   = redux_min_u32(cand);
        if (lane == 0) gout[r] = (int)wi;
        if (r == NK - 1) break;
        if ((wi & 31u) == (unsigned)lane) {      // owner updates its caches
            const int i = (int)(wi >> 5);
            sk[w][i][lane] = 0xffffffffu;
            const int g = i >> 3;
            unsigned long long gm = ~0ull;
            #pragma unroll
            for (int j = 0; j < 8; ++j) {
                const int ii = g * 8 + j;
                const unsigned long long pk =
                    ((unsigned long long)sk[w][ii][lane] << 32) | (unsigned)(ii * 32 + lane);
                gm = min(gm, pk);
            }
            sgm[w][g][lane] = gm;
            unsigned long long nlb = ~0ull;
            #pragma unroll
            for (int g2 = 0; g2 < 8; ++g2) nlb = min(nlb, sgm[w][g2][lane]);
            lb = nlb;
        }
    }
}

// ---------------------------------------------------------------------------
// per-batch sum / sumsq of centered = feat[gidx] - feat[fidx]  (float4 loads)
// ---------------------------------------------------------------------------
__global__ void zero_kernel() {
    const int t = threadIdx.x;
    if (t < BB) { g_sum[t] = 0.0; g_sq[t] = 0.0; }
}

__global__ __launch_bounds__(256)
void stats_kernel(const float* __restrict__ feat) {
    const int b = blockIdx.y;
    const float4* F4 = (const float4*)(feat + b * NP * NC);
    const int tid = blockIdx.x * 256 + threadIdx.x;   // 64*256 = 16384 threads
    const int STRIDE = 64 * 256;
    const int TOT4B = NS * NK * (NC / 4);             // 196608

    double s = 0.0, q = 0.0;
    for (int e = tid; e < TOT4B; e += STRIDE) {
        const int c4 = e & 15;
        const int sj = e >> 4;
        const int gi = g_gidx[b * NS * NK + sj];
        const int fi = g_fidx[b * NS + sj / NK];
        const float4 a = F4[gi * 16 + c4];
        const float4 m = F4[fi * 16 + c4];
        const float vx = a.x - m.x, vy = a.y - m.y, vz = a.z - m.z, vw = a.w - m.w;
        s += (double)vx + (double)vy + (double)vz + (double)vw;
        q += (double)vx * vx + (double)vy * vy + (double)vz * vz + (double)vw * vw;
    }
    const int lane = threadIdx.x & 31, wid = threadIdx.x >> 5;
    #pragma unroll
    for (int off = 16; off > 0; off >>= 1) {
        s += __shfl_down_sync(0xffffffffu, s, off);
        q += __shfl_down_sync(0xffffffffu, q, off);
    }
    __shared__ double ws[8], wq[8];
    if (lane == 0) { ws[wid] = s; wq[wid] = q; }
    __syncthreads();
    if (threadIdx.x == 0) {
        double ts = ws[0], tq = wq[0];
        #pragma unroll
        for (int w2 = 1; w2 < 8; ++w2) { ts += ws[w2]; tq += wq[w2]; }
        atomicAdd(&g_sum[b], ts);
        atomicAdd(&g_sq[b], tq);
    }
}

// ---------------------------------------------------------------------------
// finalize (float4): out[..,0:64] = alpha*(centered/(std+eps))+beta ; [64:128]=mean
// ---------------------------------------------------------------------------
__global__ __launch_bounds__(256)
void finalize_kernel(const float* __restrict__ feat,
                     const float* __restrict__ alpha,
                     const float* __restrict__ beta,
                     float* __restrict__ out) {
    const int TOT4 = BB * NS * NK * (NC / 4);
    const int gid = blockIdx.x * 256 + threadIdx.x;
    if (gid >= TOT4) return;
    const int c4  = gid & 15;
    const int sj  = gid >> 4;               // b*NS*NK + s*NK + j
    const int b   = sj / (NS * NK);
    const int rem = sj % (NS * NK);
    const int s   = rem / NK;

    const float* F = feat + b * NP * NC;
    const int gi = g_gidx[sj];
    const int fi = g_fidx[b * NS + s];

    const float4 mean = *(const float4*)(F + fi * NC + c4 * 4);
    const float4 gv   = *(const float4*)(F + gi * NC + c4 * 4);
    const float4 al   = *(const float4*)(alpha + c4 * 4);
    const float4 be   = *(const float4*)(beta  + c4 * 4);

    const double Nf  = (double)(NS * NK * NC);
    const double sum = g_sum[b], sq = g_sq[b];
    double var = (sq - sum * sum / Nf) / (Nf - 1.0);
    if (var < 0.0) var = 0.0;
    const float stdv = (float)sqrt(var);
    const float inv = 1.0f / (stdv + 1e-5f);

    float4 gf;
    gf.x = al.x * ((gv.x - mean.x) * inv) + be.x;
    gf.y = al.y * ((gv.y - mean.y) * inv) + be.y;
    gf.z = al.z * ((gv.z - mean.z) * inv) + be.z;
    gf.w = al.w * ((gv.w - mean.w) * inv) + be.w;

    float* o = out + sj * 128;
    *(float4*)(o + c4 * 4)      = gf;
    *(float4*)(o + 64 + c4 * 4) = mean;
}

// ---------------------------------------------------------------------------
extern "C" void kernel_launch(void* const* d_in, const int* in_sizes, int n_in,
                              void* d_out, int out_size) {
    const float* pts   = (const float*)d_in[0];   // 16x2048x3
    const float* feat  = (const float*)d_in[1];   // 16x2048x64
    const float* alpha = (const float*)d_in[2];   // 64
    const float* beta  = (const float*)d_in[3];   // 64
    float* out = (float*)d_out;

    const int SZ_IDX = BB * NS;
    const int SZ_SP  = BB * NS * 3;
    const int SZ_OF  = BB * NS * NK * 2 * NC;

    float* out_idx = nullptr;
    float* out_sp  = nullptr;
    float* out_f   = out;
    if (out_size >= SZ_IDX + SZ_SP + SZ_OF) {
        out_idx = out;
        out_sp  = out + SZ_IDX;
        out_f   = out + SZ_IDX + SZ_SP;
    }

    static bool attr_set = false;
    if (!attr_set) {
        cudaFuncSetAttribute(knn_kernel, cudaFuncAttributeMaxDynamicSharedMemorySize, KNN_SMEM);
        attr_set = true;
    }

    zero_kernel<<<1, 32>>>();     // independent; hides under fps

    fps_kernel<<<BB, 512>>>(pts, out_idx, out_sp);

    knn_kernel<<<BB * 64, 256, KNN_SMEM>>>(pts);

    dim3 sg(64, BB);
    stats_kernel<<<sg, 256>>>(feat);

    const int TOT4 = BB * NS * NK * (NC / 4);
    finalize_kernel<<<(TOT4 + 255) / 256, 256>>>(feat, alpha, beta, out_f);
}

// round 6
// speedup vs baseline: 2.2052x; 1.1793x over previous
#include <cuda_runtime.h>

#define BB 16      // batches
#define NP 2048    // points per batch
#define NC 64      // feature channels
#define NS 512     // fps samples
#define NK 24      // knn k

// scratch (no allocation allowed)
__device__ int    g_fidx[BB * NS];
__device__ int    g_gidx[BB * NS * NK];
__device__ double g_sum[BB];
__device__ double g_sq[BB];

__device__ __forceinline__ unsigned redux_max_u32(unsigned v) {
    unsigned r;
    asm volatile("redux.sync.max.u32 %0, %1, 0xffffffff;" : "=r"(r) : "r"(v));
    return r;
}
__device__ __forceinline__ unsigned redux_min_u32(unsigned v) {
    unsigned r;
    asm volatile("redux.sync.min.u32 %0, %1, 0xffffffff;" : "=r"(r) : "r"(v));
    return r;
}

// ---------------------------------------------------------------------------
// FPS: one block/batch, 256 threads x 8 points, all coords in registers.
// Per iteration: reg-only distances -> local argmax (tie->lowest idx) ->
// 2x redux -> lane0 STS packed u64 into parity-double-buffered slots ->
// one __syncthreads -> all threads max-combine the 8 slots.
// Key = (dist_bits << 32) | ~idx : u64 max => max dist, tie => min idx.
// Distance association identical to verified bit-exact version.
// ---------------------------------------------------------------------------
__global__ __launch_bounds__(256, 1)
void fps_kernel(const float* __restrict__ pts,
                float* __restrict__ out_idx,   // may be null
                float* __restrict__ out_sp) {  // may be null
    const int b = blockIdx.x;
    __shared__ float sp[NP * 3];                 // 24 KB
    __shared__ unsigned long long sw[2][8];

    const int t = threadIdx.x;
    {
        const float4* src = (const float4*)(pts + b * NP * 3);
        float4* dst = (float4*)sp;
        #pragma unroll
        for (int j = 0; j < 6; ++j) dst[t + j * 256] = src[t + j * 256];
    }
    __syncthreads();

    float px[8], py[8], pz[8], m[8];
    #pragma unroll
    for (int j = 0; j < 8; ++j) {
        const int i = t + j * 256;            // ascending: i(j) < i(j+1)
        px[j] = sp[3*i]; py[j] = sp[3*i+1]; pz[j] = sp[3*i+2];
        m[j] = 1e10f;
    }
    int cur = 0;
    const int wid = t >> 5, lane = t & 31;
    const bool emit_idx = (out_idx != nullptr);
    const bool emit_sp  = (out_sp  != nullptr);

    for (int it = 0; it < NS; ++it) {
        const float cx = sp[3*cur], cy = sp[3*cur+1], cz = sp[3*cur+2];
        if (t == 0) {
            g_fidx[b * NS + it] = cur;
            if (emit_idx) out_idx[b * NS + it] = (float)cur;
            if (emit_sp) {
                float* o = out_sp + (b * NS + it) * 3;
                o[0] = cx; o[1] = cy; o[2] = cz;
            }
        }
        unsigned f[8];
        #pragma unroll
        for (int j = 0; j < 8; ++j) {
            // exact reference association: ((dx*dx + dy*dy) + dz*dz)
            const float dx = px[j] - cx, dy = py[j] - cy, dz = pz[j] - cz;
            const float d = __fadd_rn(__fadd_rn(__fmul_rn(dx,dx), __fmul_rn(dy,dy)), __fmul_rn(dz,dz));
            m[j] = fminf(m[j], d);
            f[j] = __float_as_uint(m[j]);     // nonneg -> bit order == float order
        }
        unsigned bv = f[0];
        #pragma unroll
        for (int j = 1; j < 8; ++j) bv = max(bv, f[j]);
        const unsigned wm = redux_max_u32(bv);
        unsigned cand = 0xffffffffu;
        #pragma unroll
        for (int j = 7; j >= 0; --j)          // descending overwrite -> smallest idx
            if (f[j] == wm) cand = (unsigned)(t + j * 256);
        const unsigned wi = redux_min_u32(cand);
        if (lane == 0)
            sw[it & 1][wid] = ((unsigned long long)wm << 32) | (unsigned)(~wi);
        __syncthreads();
        unsigned long long best = sw[it & 1][0];
        #pragma unroll
        for (int w2 = 1; w2 < 8; ++w2) best = max(best, sw[it & 1][w2]);
        cur = (int)(~(unsigned)best);
    }
}

// ---------------------------------------------------------------------------
// kNN: warp per query, 8 warps/block, 40 KB smem (points + group minima).
// Lane l owns candidates n = i*32+l, i=0..63, split in 8 groups of 8.
// No key cache: on removal the owner lane sets a bit in its 64-bit register
// mask and RECOMPUTES the affected group's 8 distances (deterministic ->
// identical bits). Per round: 2 redux + owner-only group rebuild.
// Distance formula identical to the verified kernel.
// ---------------------------------------------------------------------------
__global__ __launch_bounds__(256)
void knn_kernel(const float* __restrict__ pts) {
    __shared__ float sp[NP * 3];                        // 24 KB
    __shared__ unsigned long long sgm[8][8][32];        // 16 KB [warp][group][lane]

    const int blk  = blockIdx.x;          // 0..1023
    const int b    = blk >> 6;
    const int sgrp = blk & 63;
    const int t = threadIdx.x, lane = t & 31, w = t >> 5;
    const int s = sgrp * 8 + w;

    {
        const float4* src = (const float4*)(pts + b * NP * 3);
        float4* dst = (float4*)sp;
        #pragma unroll
        for (int j = 0; j < 6; ++j) dst[t + j * 256] = src[t + j * 256];
    }
    __syncthreads();

    const int qi = g_fidx[b * NS + s];
    const float sx = sp[3*qi], sy = sp[3*qi+1], sz = sp[3*qi+2];
    const float d2 = __fadd_rn(__fadd_rn(__fmul_rn(sx,sx), __fmul_rn(sy,sy)), __fmul_rn(sz,sz));

    // distance -> monotonic u32 key (handles negatives from rounding)
    auto dist_key = [&](int n) -> unsigned {
        const float px = sp[3*n], py = sp[3*n+1], pz = sp[3*n+2];
        const float d1 = __fadd_rn(__fadd_rn(__fmul_rn(px,px), __fmul_rn(py,py)), __fmul_rn(pz,pz));
        const float d3 = __fmaf_rn(sz, pz, __fmaf_rn(sy, py, __fmul_rn(sx, px)));
        const float d  = __fsub_rn(__fadd_rn(d1, d2), __fmul_rn(2.0f, d3));
        const unsigned bits = __float_as_uint(d);
        return (bits & 0x80000000u) ? ~bits : (bits | 0x80000000u);
    };

    unsigned long long removed = 0ull;
    unsigned long long lb = ~0ull;
    #pragma unroll
    for (int g = 0; g < 8; ++g) {
        unsigned long long gm = ~0ull;
        #pragma unroll
        for (int j = 0; j < 8; ++j) {
            const int i = g * 8 + j;
            const int n = i * 32 + lane;
            const unsigned long long pk =
                ((unsigned long long)dist_key(n) << 32) | (unsigned)n;
            gm = min(gm, pk);                 // equal key -> lower n (low bits)
        }
        sgm[w][g][lane] = gm;
        lb = min(lb, gm);
    }

    int* gout = g_gidx + (b * NS + s) * NK;
    for (int r = 0; r < NK; ++r) {
        const unsigned lbk = (unsigned)(lb >> 32);
        const unsigned wk  = redux_min_u32(lbk);
        const unsigned cand = (lbk == wk) ? (unsigned)lb : 0xffffffffu;  // low = n
        const unsigned wi   = redux_min_u32(cand);
        if (lane == 0) gout[r] = (int)wi;
        if (r == NK - 1) break;
        if ((wi & 31u) == (unsigned)lane) {   // owner rebuilds its group
            const int i = (int)(wi >> 5);
            removed |= 1ull << i;
            const int g = i >> 3;
            unsigned long long gm = ~0ull;
            #pragma unroll
            for (int j = 0; j < 8; ++j) {
                const int ii = g * 8 + j;
                const int n = ii * 32 + lane;
                const unsigned key = (removed >> ii) & 1ull ?
                                     0xffffffffu : dist_key(n);
                const unsigned long long pk =
                    ((unsigned long long)key << 32) | (unsigned)n;
                gm = min(gm, pk);
            }
            sgm[w][g][lane] = gm;
            unsigned long long nlb = ~0ull;
            #pragma unroll
            for (int g2 = 0; g2 < 8; ++g2) nlb = min(nlb, sgm[w][g2][lane]);
            lb = nlb;
        }
    }
}

// ---------------------------------------------------------------------------
// per-batch sum / sumsq of centered = feat[gidx] - feat[fidx]  (float4 loads)
// ---------------------------------------------------------------------------
__global__ void zero_kernel() {
    const int t = threadIdx.x;
    if (t < BB) { g_sum[t] = 0.0; g_sq[t] = 0.0; }
}

#define STATS_BLKS 128

__global__ __launch_bounds__(256)
void stats_kernel(const float* __restrict__ feat) {
    const int b = blockIdx.y;
    const float4* F4 = (const float4*)(feat + b * NP * NC);
    const int tid = blockIdx.x * 256 + threadIdx.x;
    const int STRIDE = STATS_BLKS * 256;
    const int TOT4B = NS * NK * (NC / 4);             // 196608

    double s = 0.0, q = 0.0;
    for (int e = tid; e < TOT4B; e += STRIDE) {
        const int c4 = e & 15;
        const int sj = e >> 4;
        const int gi = g_gidx[b * NS * NK + sj];
        const int fi = g_fidx[b * NS + sj / NK];
        const float4 a = F4[gi * 16 + c4];
        const float4 m = F4[fi * 16 + c4];
        const float vx = a.x - m.x, vy = a.y - m.y, vz = a.z - m.z, vw = a.w - m.w;
        s += (double)vx + (double)vy + (double)vz + (double)vw;
        q += (double)vx * vx + (double)vy * vy + (double)vz * vz + (double)vw * vw;
    }
    const int lane = threadIdx.x & 31, wid = threadIdx.x >> 5;
    #pragma unroll
    for (int off = 16; off > 0; off >>= 1) {
        s += __shfl_down_sync(0xffffffffu, s, off);
        q += __shfl_down_sync(0xffffffffu, q, off);
    }
    __shared__ double ws[8], wq[8];
    if (lane == 0) { ws[wid] = s; wq[wid] = q; }
    __syncthreads();
    if (threadIdx.x == 0) {
        double ts = ws[0], tq = wq[0];
        #pragma unroll
        for (int w2 = 1; w2 < 8; ++w2) { ts += ws[w2]; tq += wq[w2]; }
        atomicAdd(&g_sum[b], ts);
        atomicAdd(&g_sq[b], tq);
    }
}

// ---------------------------------------------------------------------------
// finalize (float4): out[..,0:64] = alpha*(centered/(std+eps))+beta ; [64:128]=mean
// ---------------------------------------------------------------------------
__global__ __launch_bounds__(256)
void finalize_kernel(const float* __restrict__ feat,
                     const float* __restrict__ alpha,
                     const float* __restrict__ beta,
                     float* __restrict__ out) {
    const int TOT4 = BB * NS * NK * (NC / 4);
    const int gid = blockIdx.x * 256 + threadIdx.x;
    if (gid >= TOT4) return;
    const int c4  = gid & 15;
    const int sj  = gid >> 4;               // b*NS*NK + s*NK + j
    const int b   = sj / (NS * NK);
    const int rem = sj % (NS * NK);
    const int s   = rem / NK;

    const float* F = feat + b * NP * NC;
    const int gi = g_gidx[sj];
    const int fi = g_fidx[b * NS + s];

    const float4 mean = *(const float4*)(F + fi * NC + c4 * 4);
    const float4 gv   = *(const float4*)(F + gi * NC + c4 * 4);
    const float4 al   = *(const float4*)(alpha + c4 * 4);
    const float4 be   = *(const float4*)(beta  + c4 * 4);

    const double Nf  = (double)(NS * NK * NC);
    const double sum = g_sum[b], sq = g_sq[b];
    double var = (sq - sum * sum / Nf) / (Nf - 1.0);
    if (var < 0.0) var = 0.0;
    const float stdv = (float)sqrt(var);
    const float inv = 1.0f / (stdv + 1e-5f);

    float4 gf;
    gf.x = al.x * ((gv.x - mean.x) * inv) + be.x;
    gf.y = al.y * ((gv.y - mean.y) * inv) + be.y;
    gf.z = al.z * ((gv.z - mean.z) * inv) + be.z;
    gf.w = al.w * ((gv.w - mean.w) * inv) + be.w;

    float* o = out + sj * 128;
    *(float4*)(o + c4 * 4)      = gf;
    *(float4*)(o + 64 + c4 * 4) = mean;
}

// ---------------------------------------------------------------------------
extern "C" void kernel_launch(void* const* d_in, const int* in_sizes, int n_in,
                              void* d_out, int out_size) {
    const float* pts   = (const float*)d_in[0];   // 16x2048x3
    const float* feat  = (const float*)d_in[1];   // 16x2048x64
    const float* alpha = (const float*)d_in[2];   // 64
    const float* beta  = (const float*)d_in[3];   // 64
    float* out = (float*)d_out;

    const int SZ_IDX = BB * NS;
    const int SZ_SP  = BB * NS * 3;
    const int SZ_OF  = BB * NS * NK * 2 * NC;

    float* out_idx = nullptr;
    float* out_sp  = nullptr;
    float* out_f   = out;
    if (out_size >= SZ_IDX + SZ_SP + SZ_OF) {
        out_idx = out;
        out_sp  = out + SZ_IDX;
        out_f   = out + SZ_IDX + SZ_SP;
    }

    zero_kernel<<<1, 32>>>();     // independent; hides under fps

    fps_kernel<<<BB, 256>>>(pts, out_idx, out_sp);

    knn_kernel<<<BB * 64, 256>>>(pts);

    dim3 sg(STATS_BLKS, BB);
    stats_kernel<<<sg, 256>>>(feat);

    const int TOT4 = BB * NS * NK * (NC / 4);
    finalize_kernel<<<(TOT4 + 255) / 256, 256>>>(feat, alpha, beta, out_f);
}

// round 7
// speedup vs baseline: 2.3025x; 1.0441x over previous
#include <cuda_runtime.h>

#define BB 16      // batches
#define NP 2048    // points per batch
#define NC 64      // feature channels
#define NS 512     // fps samples
#define NK 24      // knn k

// scratch (no allocation allowed)
__device__ int    g_fidx[BB * NS];
__device__ int    g_gidx[BB * NS * NK];
__device__ double g_sum[BB];
__device__ double g_sq[BB];
__device__ float  g_inv[BB];

__device__ __forceinline__ unsigned redux_max_u32(unsigned v) {
    unsigned r;
    asm volatile("redux.sync.max.u32 %0, %1, 0xffffffff;" : "=r"(r) : "r"(v));
    return r;
}
__device__ __forceinline__ unsigned redux_min_u32(unsigned v) {
    unsigned r;
    asm volatile("redux.sync.min.u32 %0, %1, 0xffffffff;" : "=r"(r) : "r"(v));
    return r;
}

// ---------------------------------------------------------------------------
// FPS: one block/batch, 256 threads x 8 points, coords in registers.
// Per iteration: reg distances -> local argmax -> 2x redux -> lane0 STS into
// parity double-buffered slots -> one __syncthreads -> max-combine 8 slots.
// Key = (dist_bits << 32) | ~idx. Distance association bit-exact vs reference.
// Points stored in smem as float4 so the center fetch is one LDS.128.
// ---------------------------------------------------------------------------
__global__ __launch_bounds__(256, 1)
void fps_kernel(const float* __restrict__ pts,
                float* __restrict__ out_idx,   // may be null
                float* __restrict__ out_sp) {  // may be null
    const int b = blockIdx.x;
    __shared__ float4 sp4[NP];                   // 32 KB
    __shared__ unsigned long long sw[2][8];

    const int t = threadIdx.x;
    const float* P = pts + b * NP * 3;

    float px[8], py[8], pz[8], m[8];
    #pragma unroll
    for (int j = 0; j < 8; ++j) {
        const int i = t + j * 256;            // ascending: i(j) < i(j+1)
        px[j] = P[3*i]; py[j] = P[3*i+1]; pz[j] = P[3*i+2];
        sp4[i] = make_float4(px[j], py[j], pz[j], 0.f);
        m[j] = 1e10f;
    }
    __syncthreads();

    int cur = 0;
    const int wid = t >> 5, lane = t & 31;
    const bool emit_idx = (out_idx != nullptr);
    const bool emit_sp  = (out_sp  != nullptr);

    for (int it = 0; it < NS; ++it) {
        const float4 c = sp4[cur];
        if (t == 0) {
            g_fidx[b * NS + it] = cur;
            if (emit_idx) out_idx[b * NS + it] = (float)cur;
            if (emit_sp) {
                float* o = out_sp + (b * NS + it) * 3;
                o[0] = c.x; o[1] = c.y; o[2] = c.z;
            }
        }
        unsigned f[8];
        #pragma unroll
        for (int j = 0; j < 8; ++j) {
            // exact reference association: ((dx*dx + dy*dy) + dz*dz)
            const float dx = px[j] - c.x, dy = py[j] - c.y, dz = pz[j] - c.z;
            const float d = __fadd_rn(__fadd_rn(__fmul_rn(dx,dx), __fmul_rn(dy,dy)), __fmul_rn(dz,dz));
            m[j] = fminf(m[j], d);
            f[j] = __float_as_uint(m[j]);     // nonneg -> bit order == float order
        }
        unsigned bv = f[0];
        #pragma unroll
        for (int j = 1; j < 8; ++j) bv = max(bv, f[j]);
        const unsigned wm = redux_max_u32(bv);
        unsigned cand = 0xffffffffu;
        #pragma unroll
        for (int j = 7; j >= 0; --j)          // descending overwrite -> smallest idx
            if (f[j] == wm) cand = (unsigned)(t + j * 256);
        const unsigned wi = redux_min_u32(cand);
        if (lane == 0)
            sw[it & 1][wid] = ((unsigned long long)wm << 32) | (unsigned)(~wi);
        __syncthreads();
        unsigned long long best = sw[it & 1][0];
        #pragma unroll
        for (int w2 = 1; w2 < 8; ++w2) best = max(best, sw[it & 1][w2]);
        cur = (int)(~(unsigned)best);
    }
}

// ---------------------------------------------------------------------------
// kNN + fused stats. Warp per query, 8 warps/block.
// smem points packed as float4 (x, y, z, |p|^2) -> dist_key = 1 LDS.128 + fma.
// |p|^2 uses the exact reference association, so d2 (query) == sp4[qi].w.
// Per-lane group minima kept in 8 u64 REGISTERS (unrolled predicated update).
// After selection, the block gathers its 8x24 feature rows and accumulates
// per-batch sum/sumsq (double), one atomicAdd pair per block.
// ---------------------------------------------------------------------------
__global__ __launch_bounds__(256)
void knn_kernel(const float* __restrict__ pts,
                const float* __restrict__ feat) {
    __shared__ float4 sp4[NP];                 // 32 KB
    __shared__ int    sidx[8][NK];
    __shared__ int    sqi[8];
    __shared__ double ws[8], wq[8];

    const int blk  = blockIdx.x;          // 0..1023
    const int b    = blk >> 6;
    const int sgrp = blk & 63;
    const int t = threadIdx.x, lane = t & 31, w = t >> 5;
    const int s = sgrp * 8 + w;
    const float* P = pts + b * NP * 3;

    #pragma unroll
    for (int j = 0; j < 8; ++j) {
        const int i = t + j * 256;
        const float x = P[3*i], y = P[3*i+1], z = P[3*i+2];
        const float n2 = __fadd_rn(__fadd_rn(__fmul_rn(x,x), __fmul_rn(y,y)), __fmul_rn(z,z));
        sp4[i] = make_float4(x, y, z, n2);
    }
    __syncthreads();

    const int qi = g_fidx[b * NS + s];
    const float4 qp = sp4[qi];
    const float sx = qp.x, sy = qp.y, sz = qp.z;
    const float d2 = qp.w;
    if (lane == 0) sqi[w] = qi;

    // distance -> monotonic u32 key (handles small negatives from rounding)
    auto dist_key = [&](int n) -> unsigned {
        const float4 p = sp4[n];
        const float d3 = __fmaf_rn(sz, p.z, __fmaf_rn(sy, p.y, __fmul_rn(sx, p.x)));
        const float d  = __fsub_rn(__fadd_rn(p.w, d2), __fmul_rn(2.0f, d3));
        const unsigned bits = __float_as_uint(d);
        return (bits & 0x80000000u) ? ~bits : (bits | 0x80000000u);
    };

    unsigned long long removed = 0ull;
    unsigned long long gm[8];
    unsigned long long lb = ~0ull;
    #pragma unroll
    for (int g = 0; g < 8; ++g) {
        unsigned long long v = ~0ull;
        #pragma unroll
        for (int j = 0; j < 8; ++j) {
            const int i = g * 8 + j;
            const int n = i * 32 + lane;
            const unsigned long long pk =
                ((unsigned long long)dist_key(n) << 32) | (unsigned)n;
            v = min(v, pk);                 // equal key -> lower n (low bits)
        }
        gm[g] = v;
        lb = min(lb, v);
    }

    int* gout = g_gidx + (b * NS + s) * NK;
    for (int r = 0; r < NK; ++r) {
        const unsigned lbk = (unsigned)(lb >> 32);
        const unsigned wk  = redux_min_u32(lbk);
        const unsigned cand = (lbk == wk) ? (unsigned)lb : 0xffffffffu;  // low = n
        const unsigned wi   = redux_min_u32(cand);
        if (lane == 0) { gout[r] = (int)wi; sidx[w][r] = (int)wi; }
        if (r == NK - 1) break;
        if ((wi & 31u) == (unsigned)lane) {   // owner rebuilds its group
            const int i = (int)(wi >> 5);
            removed |= 1ull << i;
            const int g = i >> 3;
            unsigned long long v = ~0ull;
            #pragma unroll
            for (int j = 0; j < 8; ++j) {
                const int ii = g * 8 + j;
                const int n = ii * 32 + lane;
                const unsigned key = ((removed >> ii) & 1ull) ? 0xffffffffu : dist_key(n);
                v = min(v, ((unsigned long long)key << 32) | (unsigned)n);
            }
            #pragma unroll
            for (int gg = 0; gg < 8; ++gg) if (gg == g) gm[gg] = v;
            unsigned long long nlb = ~0ull;
            #pragma unroll
            for (int g2 = 0; g2 < 8; ++g2) nlb = min(nlb, gm[g2]);
            lb = nlb;
        }
    }
    __syncthreads();   // sidx/sqi complete for all warps

    // fused stats: this block's 8 queries x 24 neighbors x 16 float4
    {
        const float4* F4 = (const float4*)(feat + b * NP * NC);
        double s_acc = 0.0, q_acc = 0.0;
        #pragma unroll
        for (int u = 0; u < 12; ++u) {
            const int e  = t + u * 256;        // 0..3071
            const int c4 = e & 15;
            const int wj = e >> 4;             // 0..191
            const int ww = wj / NK;
            const int j  = wj % NK;
            const int gi = sidx[ww][j];
            const int fi = sqi[ww];
            const float4 a = F4[gi * 16 + c4];
            const float4 mm = F4[fi * 16 + c4];
            const float vx = a.x - mm.x, vy = a.y - mm.y, vz = a.z - mm.z, vw = a.w - mm.w;
            s_acc += (double)vx + (double)vy + (double)vz + (double)vw;
            q_acc += (double)vx * vx + (double)vy * vy + (double)vz * vz + (double)vw * vw;
        }
        #pragma unroll
        for (int off = 16; off > 0; off >>= 1) {
            s_acc += __shfl_down_sync(0xffffffffu, s_acc, off);
            q_acc += __shfl_down_sync(0xffffffffu, q_acc, off);
        }
        if (lane == 0) { ws[w] = s_acc; wq[w] = q_acc; }
        __syncthreads();
        if (t == 0) {
            double ts = ws[0], tq = wq[0];
            #pragma unroll
            for (int w2 = 1; w2 < 8; ++w2) { ts += ws[w2]; tq += wq[w2]; }
            atomicAdd(&g_sum[b], ts);
            atomicAdd(&g_sq[b], tq);
        }
    }
}

// ---------------------------------------------------------------------------
__global__ void zero_kernel() {
    const int t = threadIdx.x;
    if (t < BB) { g_sum[t] = 0.0; g_sq[t] = 0.0; }
}

__global__ void stdcalc_kernel() {
    const int t = threadIdx.x;
    if (t < BB) {
        const double Nf = (double)(NS * NK * NC);
        const double sum = g_sum[t], sq = g_sq[t];
        double var = (sq - sum * sum / Nf) / (Nf - 1.0);
        if (var < 0.0) var = 0.0;
        g_inv[t] = 1.0f / ((float)sqrt(var) + 1e-5f);
    }
}

// ---------------------------------------------------------------------------
// finalize (pure float): out[..,0:64] = alpha*(centered*inv)+beta ; [64:128]=mean
// ---------------------------------------------------------------------------
__global__ __launch_bounds__(256)
void finalize_kernel(const float* __restrict__ feat,
                     const float* __restrict__ alpha,
                     const float* __restrict__ beta,
                     float* __restrict__ out) {
    const int TOT4 = BB * NS * NK * (NC / 4);
    const int gid = blockIdx.x * 256 + threadIdx.x;
    if (gid >= TOT4) return;
    const int c4  = gid & 15;
    const int sj  = gid >> 4;               // b*NS*NK + s*NK + j
    const int b   = sj / (NS * NK);
    const int rem = sj % (NS * NK);
    const int s   = rem / NK;

    const float* F = feat + b * NP * NC;
    const int gi = g_gidx[sj];
    const int fi = g_fidx[b * NS + s];

    const float4 mean = *(const float4*)(F + fi * NC + c4 * 4);
    const float4 gv   = *(const float4*)(F + gi * NC + c4 * 4);
    const float4 al   = *(const float4*)(alpha + c4 * 4);
    const float4 be   = *(const float4*)(beta  + c4 * 4);
    const float inv   = g_inv[b];

    float4 gf;
    gf.x = al.x * ((gv.x - mean.x) * inv) + be.x;
    gf.y = al.y * ((gv.y - mean.y) * inv) + be.y;
    gf.z = al.z * ((gv.z - mean.z) * inv) + be.z;
    gf.w = al.w * ((gv.w - mean.w) * inv) + be.w;

    float* o = out + sj * 128;
    *(float4*)(o + c4 * 4)      = gf;
    *(float4*)(o + 64 + c4 * 4) = mean;
}

// ---------------------------------------------------------------------------
extern "C" void kernel_launch(void* const* d_in, const int* in_sizes, int n_in,
                              void* d_out, int out_size) {
    const float* pts   = (const float*)d_in[0];   // 16x2048x3
    const float* feat  = (const float*)d_in[1];   // 16x2048x64
    const float* alpha = (const float*)d_in[2];   // 64
    const float* beta  = (const float*)d_in[3];   // 64
    float* out = (float*)d_out;

    const int SZ_IDX = BB * NS;
    const int SZ_SP  = BB * NS * 3;
    const int SZ_OF  = BB * NS * NK * 2 * NC;

    float* out_idx = nullptr;
    float* out_sp  = nullptr;
    float* out_f   = out;
    if (out_size >= SZ_IDX + SZ_SP + SZ_OF) {
        out_idx = out;
        out_sp  = out + SZ_IDX;
        out_f   = out + SZ_IDX + SZ_SP;
    }

    zero_kernel<<<1, 32>>>();     // independent; hides under fps

    fps_kernel<<<BB, 256>>>(pts, out_idx, out_sp);

    knn_kernel<<<BB * 64, 256>>>(pts, feat);

    stdcalc_kernel<<<1, 32>>>();

    const int TOT4 = BB * NS * NK * (NC / 4);
    finalize_kernel<<<(TOT4 + 255) / 256, 256>>>(feat, alpha, beta, out_f);
}

// round 8
// speedup vs baseline: 2.4723x; 1.0738x over previous
#include <cuda_runtime.h>

#define BB 16      // batches
#define NP 2048    // points per batch
#define NC 64      // feature channels
#define NS 512     // fps samples
#define NK 24      // knn k

// scratch (no allocation allowed)
__device__ int    g_fidx[BB * NS];
__device__ int    g_gidx[BB * NS * NK];
__device__ double g_sum[BB];
__device__ double g_sq[BB];
__device__ float  g_inv[BB];
__device__ int    g_cnt = 0;

__device__ __forceinline__ unsigned redux_max_u32(unsigned v) {
    unsigned r;
    asm volatile("redux.sync.max.u32 %0, %1, 0xffffffff;" : "=r"(r) : "r"(v));
    return r;
}
__device__ __forceinline__ unsigned redux_min_u32(unsigned v) {
    unsigned r;
    asm volatile("redux.sync.min.u32 %0, %1, 0xffffffff;" : "=r"(r) : "r"(v));
    return r;
}

// Blackwell packed f32x2 ops (elementwise rn -> bit-identical to scalar rn)
#define PACK_F32X2(out, lo, hi) \
    asm("mov.b64 %0, {%1, %2};" : "=l"(out) : "r"(lo), "r"(hi))
#define UNPACK_F32X2(lo, hi, in) \
    asm("mov.b64 {%0, %1}, %2;" : "=r"(lo), "=r"(hi) : "l"(in))
#define ADD_F32X2(out, a, b) \
    asm("add.rn.f32x2 %0, %1, %2;" : "=l"(out) : "l"(a), "l"(b))
#define MUL_F32X2(out, a, b) \
    asm("mul.rn.f32x2 %0, %1, %2;" : "=l"(out) : "l"(a), "l"(b))

// ---------------------------------------------------------------------------
// FPS: one block/batch, 256 threads x 8 points (4 packed f32x2 pairs).
// dx = px + (-cx) (== px - cx exactly); xx = dx*dx; sum = (xx+yy)+zz —
// identical association to the verified bit-exact scalar version, done 2-wide.
// Per iteration: packed distances -> scalar fmin/argmax -> 2x redux ->
// lane0 STS into parity-buffered slots -> one __syncthreads -> 8-slot max.
// Block b also zeroes g_sum/g_sq[b] (replaces zero_kernel).
// ---------------------------------------------------------------------------
__global__ __launch_bounds__(256, 1)
void fps_kernel(const float* __restrict__ pts,
                float* __restrict__ out_idx,   // may be null
                float* __restrict__ out_sp) {  // may be null
    const int b = blockIdx.x;
    __shared__ float4 sp4[NP];                   // 32 KB
    __shared__ unsigned long long sw[2][8];

    const int t = threadIdx.x;
    const float* P = pts + b * NP * 3;
    if (t == 0) { g_sum[b] = 0.0; g_sq[b] = 0.0; }

    unsigned long long px2[4], py2[4], pz2[4];
    float m[8];
    #pragma unroll
    for (int k = 0; k < 4; ++k) {
        const int ilo = t + (2*k)   * 256;
        const int ihi = t + (2*k+1) * 256;
        const float xl = P[3*ilo], yl = P[3*ilo+1], zl = P[3*ilo+2];
        const float xh = P[3*ihi], yh = P[3*ihi+1], zh = P[3*ihi+2];
        sp4[ilo] = make_float4(xl, yl, zl, 0.f);
        sp4[ihi] = make_float4(xh, yh, zh, 0.f);
        PACK_F32X2(px2[k], __float_as_uint(xl), __float_as_uint(xh));
        PACK_F32X2(py2[k], __float_as_uint(yl), __float_as_uint(yh));
        PACK_F32X2(pz2[k], __float_as_uint(zl), __float_as_uint(zh));
        m[2*k] = 1e10f; m[2*k+1] = 1e10f;
    }
    __syncthreads();

    int cur = 0;
    const int wid = t >> 5, lane = t & 31;
    const bool emit_idx = (out_idx != nullptr);
    const bool emit_sp  = (out_sp  != nullptr);

    for (int it = 0; it < NS; ++it) {
        const float4 c = sp4[cur];
        if (t == 0) {
            g_fidx[b * NS + it] = cur;
            if (emit_idx) out_idx[b * NS + it] = (float)cur;
            if (emit_sp) {
                float* o = out_sp + (b * NS + it) * 3;
                o[0] = c.x; o[1] = c.y; o[2] = c.z;
            }
        }
        const unsigned nx = __float_as_uint(-c.x);
        const unsigned ny = __float_as_uint(-c.y);
        const unsigned nz = __float_as_uint(-c.z);
        unsigned long long ncx2, ncy2, ncz2;
        PACK_F32X2(ncx2, nx, nx);
        PACK_F32X2(ncy2, ny, ny);
        PACK_F32X2(ncz2, nz, nz);

        unsigned f[8];
        #pragma unroll
        for (int k = 0; k < 4; ++k) {
            unsigned long long dx2, dy2, dz2, xx, yy, zz, ss, dd;
            ADD_F32X2(dx2, px2[k], ncx2);     // px - cx (exact)
            ADD_F32X2(dy2, py2[k], ncy2);
            ADD_F32X2(dz2, pz2[k], ncz2);
            MUL_F32X2(xx, dx2, dx2);
            MUL_F32X2(yy, dy2, dy2);
            MUL_F32X2(zz, dz2, dz2);
            ADD_F32X2(ss, xx, yy);            // (dx^2 + dy^2)
            ADD_F32X2(dd, ss, zz);            // ... + dz^2
            unsigned dlo, dhi;
            UNPACK_F32X2(dlo, dhi, dd);
            m[2*k]   = fminf(m[2*k],   __uint_as_float(dlo));
            m[2*k+1] = fminf(m[2*k+1], __uint_as_float(dhi));
            f[2*k]   = __float_as_uint(m[2*k]);    // nonneg: bit order == float order
            f[2*k+1] = __float_as_uint(m[2*k+1]);
        }
        unsigned bv = f[0];
        #pragma unroll
        for (int j = 1; j < 8; ++j) bv = max(bv, f[j]);
        const unsigned wm = redux_max_u32(bv);
        unsigned cand = 0xffffffffu;
        #pragma unroll
        for (int j = 7; j >= 0; --j)          // descending overwrite -> smallest idx
            if (f[j] == wm) cand = (unsigned)(t + j * 256);
        const unsigned wi = redux_min_u32(cand);
        if (lane == 0)
            sw[it & 1][wid] = ((unsigned long long)wm << 32) | (unsigned)(~wi);
        __syncthreads();
        unsigned long long best = sw[it & 1][0];
        #pragma unroll
        for (int w2 = 1; w2 < 8; ++w2) best = max(best, sw[it & 1][w2]);
        cur = (int)(~(unsigned)best);
    }
}

// ---------------------------------------------------------------------------
// kNN + fused stats + (last block) std computation.
// Warp per query, 8 warps/block. smem float4 (x,y,z,|p|^2); dist_key = 1
// LDS.128 + fma chain (bit-identical to verified kernel). Group minima in
// registers; owner-only rebuild per round. After selection: block gathers its
// 8x24 feature rows, accumulates per-batch sum/sumsq, and the LAST block
// computes g_inv[b] = 1/(std+eps) for all batches (replaces stdcalc_kernel).
// ---------------------------------------------------------------------------
__global__ __launch_bounds__(256)
void knn_kernel(const float* __restrict__ pts,
                const float* __restrict__ feat) {
    __shared__ float4 sp4[NP];                 // 32 KB
    __shared__ int    sidx[8][NK];
    __shared__ int    sqi[8];
    __shared__ double ws[8], wq[8];
    __shared__ int    s_last;

    const int blk  = blockIdx.x;          // 0..1023
    const int b    = blk >> 6;
    const int sgrp = blk & 63;
    const int t = threadIdx.x, lane = t & 31, w = t >> 5;
    const int s = sgrp * 8 + w;
    const float* P = pts + b * NP * 3;

    #pragma unroll
    for (int j = 0; j < 8; ++j) {
        const int i = t + j * 256;
        const float x = P[3*i], y = P[3*i+1], z = P[3*i+2];
        const float n2 = __fadd_rn(__fadd_rn(__fmul_rn(x,x), __fmul_rn(y,y)), __fmul_rn(z,z));
        sp4[i] = make_float4(x, y, z, n2);
    }
    __syncthreads();

    const int qi = g_fidx[b * NS + s];
    const float4 qp = sp4[qi];
    const float sx = qp.x, sy = qp.y, sz = qp.z;
    const float d2 = qp.w;
    if (lane == 0) sqi[w] = qi;

    auto dist_key = [&](int n) -> unsigned {
        const float4 p = sp4[n];
        const float d3 = __fmaf_rn(sz, p.z, __fmaf_rn(sy, p.y, __fmul_rn(sx, p.x)));
        const float d  = __fsub_rn(__fadd_rn(p.w, d2), __fmul_rn(2.0f, d3));
        const unsigned bits = __float_as_uint(d);
        return (bits & 0x80000000u) ? ~bits : (bits | 0x80000000u);
    };

    unsigned long long removed = 0ull;
    unsigned long long gm[8];
    unsigned long long lb = ~0ull;
    #pragma unroll
    for (int g = 0; g < 8; ++g) {
        unsigned long long v = ~0ull;
        #pragma unroll
        for (int j = 0; j < 8; ++j) {
            const int i = g * 8 + j;
            const int n = i * 32 + lane;
            v = min(v, ((unsigned long long)dist_key(n) << 32) | (unsigned)n);
        }
        gm[g] = v;
        lb = min(lb, v);
    }

    int* gout = g_gidx + (b * NS + s) * NK;
    for (int r = 0; r < NK; ++r) {
        const unsigned lbk = (unsigned)(lb >> 32);
        const unsigned wk  = redux_min_u32(lbk);
        const unsigned cand = (lbk == wk) ? (unsigned)lb : 0xffffffffu;  // low = n
        const unsigned wi   = redux_min_u32(cand);
        if (lane == 0) { gout[r] = (int)wi; sidx[w][r] = (int)wi; }
        if (r == NK - 1) break;
        if ((wi & 31u) == (unsigned)lane) {   // owner rebuilds its group
            const int i = (int)(wi >> 5);
            removed |= 1ull << i;
            const int g = i >> 3;
            unsigned long long v = ~0ull;
            #pragma unroll
            for (int j = 0; j < 8; ++j) {
                const int ii = g * 8 + j;
                const int n = ii * 32 + lane;
                const unsigned key = ((removed >> ii) & 1ull) ? 0xffffffffu : dist_key(n);
                v = min(v, ((unsigned long long)key << 32) | (unsigned)n);
            }
            #pragma unroll
            for (int gg = 0; gg < 8; ++gg) if (gg == g) gm[gg] = v;
            unsigned long long nlb = ~0ull;
            #pragma unroll
            for (int g2 = 0; g2 < 8; ++g2) nlb = min(nlb, gm[g2]);
            lb = nlb;
        }
    }
    __syncthreads();   // sidx/sqi complete for all warps

    // fused stats: this block's 8 queries x 24 neighbors x 16 float4
    {
        const float4* F4 = (const float4*)(feat + b * NP * NC);
        double s_acc = 0.0, q_acc = 0.0;
        #pragma unroll
        for (int u = 0; u < 12; ++u) {
            const int e  = t + u * 256;        // 0..3071
            const int c4 = e & 15;
            const int wj = e >> 4;             // 0..191
            const int ww = wj / NK;
            const int j  = wj % NK;
            const float4 a  = F4[sidx[ww][j] * 16 + c4];
            const float4 mm = F4[sqi[ww] * 16 + c4];
            const float vx = a.x - mm.x, vy = a.y - mm.y, vz = a.z - mm.z, vw = a.w - mm.w;
            s_acc += (double)vx + (double)vy + (double)vz + (double)vw;
            q_acc += (double)vx * vx + (double)vy * vy + (double)vz * vz + (double)vw * vw;
        }
        #pragma unroll
        for (int off = 16; off > 0; off >>= 1) {
            s_acc += __shfl_down_sync(0xffffffffu, s_acc, off);
            q_acc += __shfl_down_sync(0xffffffffu, q_acc, off);
        }
        if (lane == 0) { ws[w] = s_acc; wq[w] = q_acc; }
        __syncthreads();
        if (t == 0) {
            double ts = ws[0], tq = wq[0];
            #pragma unroll
            for (int w2 = 1; w2 < 8; ++w2) { ts += ws[w2]; tq += wq[w2]; }
            atomicAdd(&g_sum[b], ts);
            atomicAdd(&g_sq[b], tq);
            __threadfence();
            const int old = atomicAdd(&g_cnt, 1);
            s_last = (old == BB * 64 - 1) ? 1 : 0;
        }
        __syncthreads();
        if (s_last) {                          // last block: compute 1/(std+eps)
            if (t < BB) {
                const double rN  = 1.0 / (double)(NS * NK * NC);
                const double rN1 = 1.0 / (double)(NS * NK * NC - 1);
                const double sum = g_sum[t], sq = g_sq[t];
                double var = (sq - sum * sum * rN) * rN1;
                if (var < 0.0) var = 0.0;
                g_inv[t] = 1.0f / ((float)sqrt(var) + 1e-5f);
            }
            if (t == 0) g_cnt = 0;             // reset for graph determinism
        }
    }
}

// ---------------------------------------------------------------------------
// finalize (pure float, streaming stores):
//   out[..,0:64] = alpha*(centered*inv)+beta ; out[..,64:128] = mean
// ---------------------------------------------------------------------------
__global__ __launch_bounds__(256)
void finalize_kernel(const float* __restrict__ feat,
                     const float* __restrict__ alpha,
                     const float* __restrict__ beta,
                     float* __restrict__ out) {
    const int TOT4 = BB * NS * NK * (NC / 4);
    const int gid = blockIdx.x * 256 + threadIdx.x;
    if (gid >= TOT4) return;
    const int c4  = gid & 15;
    const int sj  = gid >> 4;               // b*NS*NK + s*NK + j
    const int b   = sj / (NS * NK);
    const int rem = sj % (NS * NK);
    const int s   = rem / NK;

    const float* F = feat + b * NP * NC;
    const int gi = g_gidx[sj];
    const int fi = g_fidx[b * NS + s];

    const float4 mean = *(const float4*)(F + fi * NC + c4 * 4);
    const float4 gv   = *(const float4*)(F + gi * NC + c4 * 4);
    const float4 al   = *(const float4*)(alpha + c4 * 4);
    const float4 be   = *(const float4*)(beta  + c4 * 4);
    const float inv   = g_inv[b];

    float4 gf;
    gf.x = al.x * ((gv.x - mean.x) * inv) + be.x;
    gf.y = al.y * ((gv.y - mean.y) * inv) + be.y;
    gf.z = al.z * ((gv.z - mean.z) * inv) + be.z;
    gf.w = al.w * ((gv.w - mean.w) * inv) + be.w;

    float* o = out + sj * 128;
    __stcs((float4*)(o + c4 * 4), gf);
    __stcs((float4*)(o + 64 + c4 * 4), mean);
}

// ---------------------------------------------------------------------------
extern "C" void kernel_launch(void* const* d_in, const int* in_sizes, int n_in,
                              void* d_out, int out_size) {
    const float* pts   = (const float*)d_in[0];   // 16x2048x3
    const float* feat  = (const float*)d_in[1];   // 16x2048x64
    const float* alpha = (const float*)d_in[2];   // 64
    const float* beta  = (const float*)d_in[3];   // 64
    float* out = (float*)d_out;

    const int SZ_IDX = BB * NS;
    const int SZ_SP  = BB * NS * 3;
    const int SZ_OF  = BB * NS * NK * 2 * NC;

    float* out_idx = nullptr;
    float* out_sp  = nullptr;
    float* out_f   = out;
    if (out_size >= SZ_IDX + SZ_SP + SZ_OF) {
        out_idx = out;
        out_sp  = out + SZ_IDX;
        out_f   = out + SZ_IDX + SZ_SP;
    }

    fps_kernel<<<BB, 256>>>(pts, out_idx, out_sp);

    knn_kernel<<<BB * 64, 256>>>(pts, feat);

    const int TOT4 = BB * NS * NK * (NC / 4);
    finalize_kernel<<<(TOT4 + 255) / 256, 256>>>(feat, alpha, beta, out_f);
}